// round 4
// baseline (speedup 1.0000x reference)
#include <cuda_runtime.h>
#include <cuda_bf16.h>
#include <cstdint>

// LocalitySensitiveHashing_29111288333011
//
// Mathematical collapse (holds for ALL inputs): the einsum has no contracted
// index; |sim| <= 1/hash_bits = 4.88e-4 < SIM_THRESHOLD=0.3, so the output is
// identically zeros([2,2048,2048], f32). The kernel is a pure 32 MiB zero-fill.
//
// Evidence so far: STG.128 x1/thread, STG.128 x8/thread, and driver memset all
// pin at ~4.3 TB/s (7.8 us kernel) — all three go through the SM L1tex store
// path (~32 B/cyc/SM x 148 SMs ~ 4.7 TB/s @ ~1GHz, matching). This round
// bypasses L1tex: TMA bulk stores (cp.async.bulk shared::cta -> global) are
// serviced by the per-SM TMA engine straight into L2 (LTS cap ~6300 B/cyc,
// path-independent), so the fill should approach the LTS ceiling instead.

#define ZB_THREADS 256
#define ZB_CHUNK   32768   // bytes per CTA's bulk store (16B-aligned, fits smem)

__global__ __launch_bounds__(ZB_THREADS)
void lsh_tma_zero_kernel(char* __restrict__ out, long long total_bytes) {
    __shared__ __align__(128) char buf[ZB_CHUNK];

    // Cooperatively zero the smem staging buffer (on-chip, cheap).
    float4 z = make_float4(0.f, 0.f, 0.f, 0.f);
    #pragma unroll
    for (int j = 0; j < ZB_CHUNK / (ZB_THREADS * 16); j++) {
        reinterpret_cast<float4*>(buf)[j * ZB_THREADS + threadIdx.x] = z;
    }
    __syncthreads();
    // Make generic-proxy smem writes visible to the async (TMA) proxy.
    asm volatile("fence.proxy.async.shared::cta;" ::: "memory");

    long long base = (long long)blockIdx.x * ZB_CHUNK;
    if (base >= total_bytes) return;
    long long remain = total_bytes - base;
    unsigned int bytes = (remain >= ZB_CHUNK) ? ZB_CHUNK
                        : (unsigned int)(remain & ~15LL);   // bulk size must be %16

    if (threadIdx.x == 0 && bytes > 0) {
        uint32_t saddr;
        asm("{ .reg .u64 t; cvta.to.shared.u64 t, %1; cvt.u32.u64 %0, t; }"
            : "=r"(saddr) : "l"(buf));
        asm volatile(
            "cp.async.bulk.global.shared::cta.bulk_group [%0], [%1], %2;"
            :: "l"(out + base), "r"(saddr), "r"(bytes) : "memory");
        asm volatile("cp.async.bulk.commit_group;" ::: "memory");
        asm volatile("cp.async.bulk.wait_group.read 0;" ::: "memory");
    }

    // Scalar tail for any bytes past the 16B-aligned bulk region (none for
    // this shape: 32 MiB is an exact multiple of 32 KB).
    if (remain < ZB_CHUNK) {
        for (long long i = bytes + threadIdx.x; i < remain; i += ZB_THREADS) {
            out[base + i] = 0;
        }
    }
}

extern "C" void kernel_launch(void* const* d_in, const int* in_sizes, int n_in,
                              void* d_out, int out_size) {
    (void)d_in; (void)in_sizes; (void)n_in;

    long long total_bytes = (long long)out_size * (long long)sizeof(float); // 33554432
    long long blocks = (total_bytes + ZB_CHUNK - 1) / ZB_CHUNK;             // 1024
    lsh_tma_zero_kernel<<<(unsigned int)blocks, ZB_THREADS>>>(
        (char*)d_out, total_bytes);
}

// round 5
// speedup vs baseline: 1.2362x; 1.2362x over previous
#include <cuda_runtime.h>
#include <cuda_bf16.h>

// LocalitySensitiveHashing_29111288333011
//
// Mathematical collapse (holds for ALL inputs): the 'bqhk,bkhk->bhqk' einsum
// has no contracted index (repeated k = diagonal), so sim is an elementwise
// product of sign() values in {-1,0,+1}, scaled by 1/hash_bits (2048) and
// averaged over 8 heads: |sim| <= 1/2048 = 4.88e-4 < SIM_THRESHOLD = 0.3.
// (sim > 0.3) is identically False -> output == zeros([2,2048,2048], f32).
// The optimal kernel is a pure 32 MiB zero-fill; no input is read.
//
// Measured wall: four independent write paths (STG x1/thread, STG x8/thread,
// driver memset node, TMA bulk store) all pin at ~4.3 TB/s (7.8 us kernel)
// with DRAM at 0% — the L2 write cap at bench clocks. This final form is the
// lowest-overhead SM-store formulation: exact-cover grid (no predication on
// the hot path), streaming stores (__stcs), 32-bit indexing.

#define ZF_THREADS 256
#define ZF_V       8                       // float4 per thread
#define ZF_TILE    (ZF_THREADS * ZF_V)     // 2048 float4 per block

__global__ __launch_bounds__(ZF_THREADS)
void lsh_zero_exact_kernel(float4* __restrict__ out) {
    // Exact-cover launch: no bounds checks at all.
    unsigned int base = blockIdx.x * ZF_TILE + threadIdx.x;
    const float4 z = make_float4(0.0f, 0.0f, 0.0f, 0.0f);
    #pragma unroll
    for (int j = 0; j < ZF_V; j++) {
        __stcs(out + base + j * ZF_THREADS, z);   // st.global.cs.v4 (streaming)
    }
}

__global__ void lsh_zero_tail_kernel(float* __restrict__ out, long long n) {
    long long i = (long long)blockIdx.x * blockDim.x + threadIdx.x;
    if (i < n) out[i] = 0.0f;
}

extern "C" void kernel_launch(void* const* d_in, const int* in_sizes, int n_in,
                              void* d_out, int out_size) {
    (void)d_in; (void)in_sizes; (void)n_in;

    float* out = (float*)d_out;
    long long n = (long long)out_size;       // 8,388,608 for this problem

    long long n4      = n >> 2;              // float4 count (2,097,152)
    long long blocks  = n4 / ZF_TILE;        // exact-cover blocks (1024)
    long long covered = blocks * (long long)ZF_TILE * 4;  // floats covered

    if (blocks > 0) {
        lsh_zero_exact_kernel<<<(unsigned int)blocks, ZF_THREADS>>>((float4*)out);
    }
    long long rem = n - covered;             // 0 for this shape
    if (rem > 0) {
        long long tb = (rem + 255) / 256;
        lsh_zero_tail_kernel<<<(unsigned int)tb, 256>>>(out + covered, rem);
    }
}